// round 12
// baseline (speedup 1.0000x reference)
#include <cuda_runtime.h>
#include <math.h>

// ---------------------------------------------------------------------------
// SMModel — factored GEMM on tensor cores (mma.sync.m16n8k8 tf32, 3xtf32).
//   out[o,p] = sum_d img[p+d] * U[(d,o),p] + bias-term
//   U = V[208 x 72] @ Xpatch[72 x Npx]   (V row = d*8+o; rows 200..207 = bias)
// Per (b,tile 32x16): one block, 256 thr, all 8 o computed together.
// Epilogue is register-resident: C-frag rows (r, r+8) share o, adjacent d.
// Border pixels recomputed exactly by scalar border path (cls tables).
// ---------------------------------------------------------------------------

#define NC  8
#define HID 20

__device__ __align__(16) float g_buf[5064832];

// float offsets into g_buf
#define OFF_IMG1   0
#define OFF_IMG2   32768
#define OFF_X0A    40960
#define OFF_X0B    (OFF_X0A + 1048576)
#define OFF_X1A    (OFF_X0B + 1048576)
#define OFF_X1B    (OFF_X1A + 262144)
#define OFF_X2A    (OFF_X1B + 262144)
#define OFF_X2B    (OFF_X2A + 65536)
#define OFF_TABW5  (OFF_X2B + 65536)          // 13*129600
#define OFF_TABB   (OFF_TABW5 + 1684800)      // 13*5184
#define OFF_AFHI   (OFF_TABB + 67392)         // 13*14976
#define OFF_AFLO   (OFF_AFHI + 194688)        // 13*14976

__device__ __forceinline__ float elu_f(float v) {
    return v > 0.f ? v : (expf(v) - 1.f);
}
__device__ __forceinline__ unsigned tf32_of(float x) {
    unsigned u; asm("cvt.rna.tf32.f32 %0, %1;" : "=r"(u) : "f"(x)); return u;
}
__device__ __forceinline__ void mma_tf32(float (&c)[4], const uint4& a,
                                         unsigned b0, unsigned b1) {
    asm volatile(
        "mma.sync.aligned.m16n8k8.row.col.f32.tf32.tf32.f32 "
        "{%0,%1,%2,%3}, {%4,%5,%6,%7}, {%8,%9}, {%0,%1,%2,%3};"
        : "+f"(c[0]), "+f"(c[1]), "+f"(c[2]), "+f"(c[3])
        : "r"(a.x), "r"(a.y), "r"(a.z), "r"(a.w), "r"(b0), "r"(b1));
}

// ---------------------------------------------------------------------------
// compose: effective 5x5 tables per (layer, cls, g, k). cls0 feeds vpack;
// all cls feed the scalar border path.
// ---------------------------------------------------------------------------
__global__ void compose_kernel(
    const float* __restrict__ iW1, const float* __restrict__ ib1,
    const float* __restrict__ iW2, const float* __restrict__ ib2,
    const float* __restrict__ bW1, const float* __restrict__ bb1,
    const float* __restrict__ bW2, const float* __restrict__ bb2,
    float* __restrict__ tabW5, float* __restrict__ tabB)
{
    int idx = blockIdx.x * blockDim.x + threadIdx.x;
    if (idx >= 13 * 5184) return;
    int l = idx / 5184;
    int r0 = idx % 5184;
    int cls = r0 / 576;
    int g = (r0 % 576) / 9, k = r0 % 9;
    if (l == 0 && g >= 8) return;

    const float *W1, *b1, *W2, *b2;
    if (l == 0) { W1 = iW1; b1 = ib1; W2 = iW2; b2 = ib2; }
    else {
        int m = l - 1;
        W1 = bW1 + (size_t)m * 1280 * 9;  b1 = bb1 + (size_t)m * 1280;
        W2 = bW2 + (size_t)m * 576 * 180; b2 = bb2 + (size_t)m * 576;
    }

    float T[25];
#pragma unroll
    for (int j = 0; j < 25; j++) T[j] = 0.f;
    float bias = b2[g * 9 + k];

    for (int q = 0; q < 9; q++) {
        int qy = q / 3 - 1, qx = q % 3 - 1;
        bool vyl = (qy >= 0), vyh = (qy <= 0), vxl = (qx >= 0), vxh = (qx <= 0);
        bool in;
        switch (cls) {
            case 0: in = true; break;
            case 1: in = vyl; break;
            case 2: in = vyh; break;
            case 3: in = vxl; break;
            case 4: in = vxh; break;
            case 5: in = vyl && vxl; break;
            case 6: in = vyl && vxh; break;
            case 7: in = vyh && vxl; break;
            default: in = vyh && vxh; break;
        }
        if (!in) continue;
        for (int c = 0; c < HID; c++) {
            float w2 = W2[((size_t)(g * 9 + k) * HID + c) * 9 + q];
            bias += b1[g * HID + c] * w2;
#pragma unroll
            for (int r = 0; r < 9; r++) {
                int ry = r / 3 - 1, rx = r % 3 - 1;
                T[(qy + ry + 2) * 5 + (qx + rx + 2)] += w2 * W1[(size_t)(g * HID + c) * 9 + r];
            }
        }
    }

    float* To = tabW5 + (size_t)l * 129600 + ((size_t)(cls * 64 + g) * 9 + k) * 25;
#pragma unroll
    for (int j = 0; j < 25; j++) To[j] = T[j];
    tabB[(size_t)l * 5184 + (size_t)(cls * 64 + g) * 9 + k] = bias;
}

// ---------------------------------------------------------------------------
// vpack: build fragment-ordered A matrices (hi + lo tf32) per layer.
// V[r][c]: r<200: (d=r/8, o=r%8) -> T[g(o,i)][kk][d]; r>=200: bias row o=r-200.
// c: i = c/9, kk = c%9. A-frag: thread per (lyr,m,ks,lane), 4 values:
//   q0 (r=16m+l/4, c=8ks+l%4), q1 (r+8, c), q2 (r, c+4), q3 (r+8, c+4)
// ---------------------------------------------------------------------------
__device__ __forceinline__ float vval(const float* __restrict__ tabW5,
                                      const float* __restrict__ tabB,
                                      int lyr, int nc, int r, int c)
{
    int i = c / 9, kk = c % 9;
    if (i >= nc) return 0.f;
    if (r < 200) {
        int d = r >> 3, o = r & 7;
        int g = (nc == 1) ? o : (o * 8 + i);
        return tabW5[(size_t)lyr * 129600 + ((size_t)g * 9 + kk) * 25 + d];
    }
    int o = r - 200;
    int g = (nc == 1) ? o : (o * 8 + i);
    return tabB[(size_t)lyr * 5184 + (size_t)g * 9 + kk];
}

__global__ void vpack_kernel(const float* __restrict__ tabW5,
                             const float* __restrict__ tabB,
                             float* __restrict__ afHi, float* __restrict__ afLo)
{
    int idx = blockIdx.x * blockDim.x + threadIdx.x;
    if (idx >= 13 * 13 * 9 * 32) return;
    int lyr = idx / (13 * 9 * 32);
    int rem = idx % (13 * 9 * 32);
    int m = rem / (9 * 32);
    int r2 = rem % (9 * 32);
    int ks = r2 / 32, lane = r2 % 32;
    int nc = (lyr == 0) ? 1 : 8;

    int rb = m * 16 + (lane >> 2);
    int cb = ks * 8 + (lane & 3);
    float v[4];
    v[0] = vval(tabW5, tabB, lyr, nc, rb,     cb);
    v[1] = vval(tabW5, tabB, lyr, nc, rb + 8, cb);
    v[2] = vval(tabW5, tabB, lyr, nc, rb,     cb + 4);
    v[3] = vval(tabW5, tabB, lyr, nc, rb + 8, cb + 4);

    size_t base = ((size_t)(lyr * 117 + m * 9 + ks) * 32 + lane) * 4;
#pragma unroll
    for (int q = 0; q < 4; q++) {
        unsigned hi = tf32_of(v[q]);
        float lof = v[q] - __uint_as_float(hi);
        afHi[base + q] = __uint_as_float(hi);
        afLo[base + q] = __uint_as_float(tf32_of(lof));
    }
}

// ---------------------------------------------------------------------------
// main TC kernel + fused scalar border. 256 thr. Tile = 32 wide x 16 tall.
// mode0: 32 main (full only) + 2 border. mode1: 42 main (32+8+2) + 4 border.
// dynamic smem: simg 2880 | slut 288(+pad) | sAhi 59904 | sAlo 59904 = 123008
// ---------------------------------------------------------------------------
__global__ __launch_bounds__(256) void smtc_kernel(
    const float* __restrict__ img0, const float* __restrict__ img1p, const float* __restrict__ img2p,
    const float* __restrict__ xin0, const float* __restrict__ xin1, const float* __restrict__ xin2,
    float* __restrict__ out0, float* __restrict__ out1, float* __restrict__ out2,
    const float* __restrict__ afHi, const float* __restrict__ afLo,
    const float* __restrict__ tabW5, const float* __restrict__ tabB,
    int nc_in, int slotBase, int mode)
{
    const int bx = blockIdx.x;
    const int b = blockIdx.z;
    const int tid = threadIdx.x;
    const int mainX = (mode == 0) ? 32 : 42;

    if (bx >= mainX) {
        // ---------------- scalar border path (exact, cls tables) ----------
        int bp = (bx - mainX) * 256 + tid;
        int limit = (mode == 0) ? 508 : 884;
        if (bp >= limit) return;
        int s, e;
        if (bp < 508)      { s = 0; e = bp; }
        else if (bp < 760) { s = 1; e = bp - 508; }
        else               { s = 2; e = bp - 760; }
        const float* img = (s == 0) ? img0 : (s == 1) ? img1p : img2p;
        const float* xin = (s == 0) ? xin0 : (s == 1) ? xin1 : xin2;
        float* out = (s == 0) ? out0 : (s == 1) ? out1 : out2;
        const int N = 128 >> s;
        const int slot = slotBase + s;

        int py, px;
        if (e < N)              { py = 0;     px = e; }
        else if (e < 2 * N)     { py = N - 1; px = e - N; }
        else if (e < 3 * N - 2) { py = e - 2 * N + 1;       px = 0; }
        else                    { py = e - (3 * N - 2) + 1; px = N - 1; }

        bool Tt = (py == 0), Bb = (py == N - 1), Ll = (px == 0), Rr = (px == N - 1);
        int cls = Tt ? (Ll ? 5 : (Rr ? 6 : 1))
                     : (Bb ? (Ll ? 7 : (Rr ? 8 : 2)) : (Ll ? 3 : 4));

        // each border output b,o: loop o here since M-folding isn't used
        float w[25];
        const float* ibp = img + (size_t)b * N * N;
#pragma unroll
        for (int dy = 0; dy < 5; dy++)
#pragma unroll
            for (int dx = 0; dx < 5; dx++) {
                int iy = py - 2 + dy, ix = px - 2 + dx;
                w[dy * 5 + dx] = (iy >= 0 && iy < N && ix >= 0 && ix < N) ? ibp[iy * N + ix] : 0.f;
            }

        for (int o = 0; o < NC; o++) {
            float accv = 0.f;
            for (int i = 0; i < nc_in; i++) {
                int g = (nc_in == 1) ? o : (o * 8 + i);
                const float* tb = tabW5 + (size_t)slot * 129600 + ((size_t)(cls * 64 + g) * 9) * 25;
                const float* bb = tabB + (size_t)slot * 5184 + (size_t)(cls * 64 + g) * 9;
                const float* xb = xin + ((size_t)b * nc_in + i) * N * N;
                float Kf[9];
#pragma unroll
                for (int k = 0; k < 9; k++) Kf[k] = bb[k];
#pragma unroll
                for (int j = 0; j < 25; j++) {
                    float v = w[j];
#pragma unroll
                    for (int k = 0; k < 9; k++) Kf[k] += tb[k * 25 + j] * v;
                }
#pragma unroll
                for (int k = 0; k < 9; k++) {
                    int yy = py + k / 3 - 1, xx = px + k % 3 - 1;
                    float xv = (yy >= 0 && yy < N && xx >= 0 && xx < N) ? xb[yy * N + xx] : 0.f;
                    accv += Kf[k] * xv;
                }
            }
            out[((size_t)b * NC + o) * N * N + py * N + px] = elu_f(accv);
        }
        return;
    }

    // ---------------- main tensor-core path ----------------
    extern __shared__ __align__(16) char smraw[];
    float* simg = (float*)smraw;                 // 20*36 floats = 2880 B
    int*   slut = (int*)(smraw + 2880);          // 72 ints (pad to 320 B)
    float* sAhi = (float*)(smraw + 3200);        // 14976 f = 59904 B
    float* sAlo = (float*)(smraw + 63104);       // 14976 f

    int s, tile;
    const float *img, *xin;
    float* out;
    if (mode == 0)    { s = 0; tile = bx; img = img0; xin = xin0; out = out0; }
    else if (bx < 32) { s = 0; tile = bx;      img = img0;  xin = xin0; out = out0; }
    else if (bx < 40) { s = 1; tile = bx - 32; img = img1p; xin = xin1; out = out1; }
    else              { s = 2; tile = bx - 40; img = img2p; xin = xin2; out = out2; }
    const int N = 128 >> s;
    const int tilesX = N / 32;
    const int tx0 = (tile % tilesX) * 32;
    const int ty0 = (tile / tilesX) * 16;
    const int slot = slotBase + s;

    // stage: image tile (halo 2, zero-padded)
    const float* ib = img + (size_t)b * N * N;
    for (int i = tid; i < 720; i += 256) {
        int ly = i / 36, lx = i % 36;
        int gy = ty0 - 2 + ly, gx = tx0 - 2 + lx;
        simg[i] = (gy >= 0 && gy < N && gx >= 0 && gx < N) ? ib[gy * N + gx] : 0.f;
    }
    // krow -> (i, ky+1, kx+1) LUT
    if (tid < 72) {
        int i = tid / 9, kk = tid % 9;
        slut[tid] = (i << 6) | ((kk / 3) << 3) | (kk % 3);
    }
    // A fragments for this layer slot
    {
        const float4* gHi = (const float4*)(afHi + (size_t)slot * 14976);
        const float4* gLo = (const float4*)(afLo + (size_t)slot * 14976);
        float4* dHi = (float4*)sAhi;
        float4* dLo = (float4*)sAlo;
        for (int i = tid; i < 3744; i += 256) { dHi[i] = gHi[i]; dLo[i] = gLo[i]; }
    }
    __syncthreads();

    const int warp = tid >> 5, lane = tid & 31;
    const int lq = lane >> 2, lr = lane & 3;       // lq=lane/4 (o / B-col), lr=lane%4
    const int ksmax = (nc_in == 1) ? 2 : 9;        // init: only i=0 rows live (krow<=8)

#pragma unroll 1
    for (int g = 0; g < 4; g++) {
        const int gg = warp * 4 + g;   // 16-pixel group (2 n-tiles)

        // ---- build B fragments (hi/lo tf32) for both n-tiles ----
        unsigned bhi[2][9][2], blo[2][9][2];
#pragma unroll
        for (int j = 0; j < 2; j++) {
            int pB = gg * 16 + j * 8 + lq;         // B col n = lane/4
            int pyB = pB >> 5, pxB = pB & 31;
#pragma unroll
            for (int ks = 0; ks < 9; ks++) {
                if (ks < ksmax) {
#pragma unroll
                    for (int h = 0; h < 2; h++) {
                        int krow = ks * 8 + lr + h * 4;   // B row k = lane%4 (+4)
                        int v = slut[krow];
                        int ii = v >> 6;
                        int ky = ((v >> 3) & 7) - 1, kx = (v & 7) - 1;
                        int gy = ty0 + pyB + ky, gx = tx0 + pxB + kx;
                        float xv = 0.f;
                        if (ii < nc_in && gy >= 0 && gy < N && gx >= 0 && gx < N)
                            xv = __ldg(xin + ((size_t)(b * nc_in + ii) * N + gy) * N + gx);
                        unsigned hi = tf32_of(xv);
                        float lof = xv - __uint_as_float(hi);
                        bhi[j][ks][h] = hi;
                        blo[j][ks][h] = tf32_of(lof);
                    }
                } else {
                    bhi[j][ks][0] = bhi[j][ks][1] = 0u;
                    blo[j][ks][0] = blo[j][ks][1] = 0u;
                }
            }
        }

        float outv[2][2] = {{0.f, 0.f}, {0.f, 0.f}};

#pragma unroll
        for (int m = 0; m < 13; m++) {
            float c[2][4] = {{0.f,0.f,0.f,0.f},{0.f,0.f,0.f,0.f}};
#pragma unroll
            for (int ks = 0; ks < 9; ks++) {
                if (ks >= ksmax) continue;
                const uint4 Ah = ((const uint4*)sAhi)[(m * 9 + ks) * 32 + lane];
                const uint4 Al = ((const uint4*)sAlo)[(m * 9 + ks) * 32 + lane];
#pragma unroll
                for (int j = 0; j < 2; j++) {
                    mma_tf32(c[j], Ah, bhi[j][ks][0], bhi[j][ks][1]);
                    mma_tf32(c[j], Ah, blo[j][ks][0], blo[j][ks][1]);
                    mma_tf32(c[j], Al, bhi[j][ks][0], bhi[j][ks][1]);
                }
            }
            // ---- register epilogue for this m-tile ----
            // rows: r0 = 16m + lq (d0 = 2m), r1 = r0+8 (d1 = 2m+1 or bias @ m=12)
            const int d0 = 2 * m, d1 = 2 * m + 1;
            const int dy0 = d0 / 5 - 2, dx0 = d0 % 5 - 2;
            const int dy1 = d1 / 5 - 2, dx1 = d1 % 5 - 2;
#pragma unroll
            for (int j = 0; j < 2; j++) {
                int pp = gg * 16 + j * 8 + lr * 2;       // C cols = (lane%4)*2, +1
                int pyr = (pp >> 5) + 2, pxc = (pp & 31) + 2;
                float w00 = simg[(pyr + dy0) * 36 + pxc + dx0];
                float w01 = simg[(pyr + dy0) * 36 + pxc + 1 + dx0];
                float w10, w11;
                if (m < 12) {
                    w10 = simg[(pyr + dy1) * 36 + pxc + dx1];
                    w11 = simg[(pyr + dy1) * 36 + pxc + 1 + dx1];
                } else {
                    w10 = 1.f; w11 = 1.f;                // bias rows
                }
                outv[j][0] += w00 * c[j][0] + w10 * c[j][2];
                outv[j][1] += w01 * c[j][1] + w11 * c[j][3];
            }
        }

        // ---- store (interior only; o = lane/4) ----
#pragma unroll
        for (int j = 0; j < 2; j++) {
            int pp = gg * 16 + j * 8 + lr * 2;
            int gy = ty0 + (pp >> 5), gx = tx0 + (pp & 31);
            if (gy > 0 && gy < N - 1) {
                float* ob = out + ((size_t)(b * NC + lq) * N + gy) * N;
                if (gx > 0 && gx < N - 1)         ob[gx]     = elu_f(outv[j][0]);
                if (gx + 1 > 0 && gx + 1 < N - 1) ob[gx + 1] = elu_f(outv[j][1]);
            }
        }
    }
}

// ---------------------------------------------------------------------------
__global__ void down_kernel(const float* __restrict__ in, float* __restrict__ out,
                            int C, int No)
{
    int idx = blockIdx.x * blockDim.x + threadIdx.x;
    int total = C * No * No;
    if (idx >= total) return;
    int c = idx / (No * No);
    int p = idx % (No * No);
    int h = p / No, w = p % No;
    int Ni = No * 2;
    const float* ib = in + (size_t)c * Ni * Ni;
    float sv = ib[(2 * h) * Ni + 2 * w] + ib[(2 * h) * Ni + 2 * w + 1]
             + ib[(2 * h + 1) * Ni + 2 * w] + ib[(2 * h + 1) * Ni + 2 * w + 1];
    out[idx] = 0.25f * sv;
}

__global__ void combine_kernel(const float* __restrict__ x0,
                               const float* __restrict__ x1,
                               const float* __restrict__ x2,
                               const float* __restrict__ w5, const float* __restrict__ b5,
                               const float* __restrict__ w6, const float* __restrict__ b6,
                               float* __restrict__ out)
{
    int idx = blockIdx.x * blockDim.x + threadIdx.x;
    if (idx >= 8 * 128 * 128) return;
    int b = idx / (128 * 128);
    int p = idx % (128 * 128);
    int h = p / 128, w = p % 128;
    float v[NC];
#pragma unroll
    for (int c = 0; c < NC; c++) {
        v[c] = x0[((size_t)b * NC + c) * 16384 + p]
             + x1[((size_t)b * NC + c) * 4096 + (h >> 1) * 64 + (w >> 1)]
             + x2[((size_t)b * NC + c) * 1024 + (h >> 2) * 32 + (w >> 2)];
    }
    float accv = b6[0];
#pragma unroll
    for (int o = 0; o < NC; o++) {
        float y = b5[o];
#pragma unroll
        for (int c = 0; c < NC; c++) y += w5[o * NC + c] * v[c];
        y = elu_f(y);
        accv += w6[o] * y;
    }
    out[idx] = accv;
}

// ---------------------------------------------------------------------------
extern "C" void kernel_launch(void* const* d_in, const int* in_sizes, int n_in,
                              void* d_out, int out_size)
{
    const float* image = (const float*)d_in[0];
    const float* x_in  = (const float*)d_in[1];
    const float* iW1   = (const float*)d_in[2];
    const float* ib1   = (const float*)d_in[3];
    const float* iW2   = (const float*)d_in[4];
    const float* ib2   = (const float*)d_in[5];
    const float* bW1   = (const float*)d_in[6];
    const float* bb1   = (const float*)d_in[7];
    const float* bW2   = (const float*)d_in[8];
    const float* bb2   = (const float*)d_in[9];
    const float* w5    = (const float*)d_in[10];
    const float* b5    = (const float*)d_in[11];
    const float* w6    = (const float*)d_in[12];
    const float* b6    = (const float*)d_in[13];

    float* base;
    cudaGetSymbolAddress((void**)&base, g_buf);
    float* img1  = base + OFF_IMG1;
    float* img2  = base + OFF_IMG2;
    float* x0a   = base + OFF_X0A;
    float* x0b   = base + OFF_X0B;
    float* x1a   = base + OFF_X1A;
    float* x1b   = base + OFF_X1B;
    float* x2a   = base + OFF_X2A;
    float* x2b   = base + OFF_X2B;
    float* tabW5 = base + OFF_TABW5;
    float* tabB  = base + OFF_TABB;
    float* afHi  = base + OFF_AFHI;
    float* afLo  = base + OFF_AFLO;

    static int smem_set = 0;
    const int SMEM = 123008;
    if (!smem_set) {
        cudaFuncSetAttribute(smtc_kernel,
                             cudaFuncAttributeMaxDynamicSharedMemorySize, SMEM);
        smem_set = 1;
    }

    // tables + fragment pack, all layers upfront (x-independent)
    compose_kernel<<<(13 * 5184 + 127) / 128, 128>>>(
        iW1, ib1, iW2, ib2, bW1, bb1, bW2, bb2, tabW5, tabB);
    vpack_kernel<<<(13 * 13 * 9 * 32 + 127) / 128, 128>>>(tabW5, tabB, afHi, afLo);

    // image pyramid
    down_kernel<<<(8 * 64 * 64 + 255) / 256, 256>>>(image, img1, 8, 64);
    down_kernel<<<(8 * 32 * 32 + 255) / 256, 256>>>(img1, img2, 8, 32);

    // init block (slot 0, nc_in=1, full-res only): 32 main + 2 border
    smtc_kernel<<<dim3(34, 1, 8), 256, SMEM>>>(image, img1, img2,
        x_in, x_in, x_in, x0a, x0a, x0a, afHi, afLo, tabW5, tabB, 1, 0, 0);

    // downsample x
    down_kernel<<<(64 * 64 * 64 + 255) / 256, 256>>>(x0a, x1a, 64, 64);
    down_kernel<<<(64 * 32 * 32 + 255) / 256, 256>>>(x1a, x2a, 64, 32);

    float *xc = x0a, *xn = x0b;
    float *x1c = x1a, *x1n = x1b;
    float *x2c = x2a, *x2n = x2b;

    for (int t = 0; t < 4; t++) {
        // 42 main (32 full + 8 mid + 2 small) + 4 border
        smtc_kernel<<<dim3(46, 1, 8), 256, SMEM>>>(image, img1, img2,
            xc, x1c, x2c, xn, x1n, x2n, afHi, afLo, tabW5, tabB,
            8, 1 + 3 * t, 1);
        { float* tp = xc;  xc = xn;   xn = tp; }
        { float* tp = x1c; x1c = x1n; x1n = tp; }
        { float* tp = x2c; x2c = x2n; x2n = tp; }
    }

    combine_kernel<<<(8 * 128 * 128 + 255) / 256, 256>>>(
        xc, x1c, x2c, w5, b5, w6, b6, (float*)d_out);
}